// round 15
// baseline (speedup 1.0000x reference)
#include <cuda_runtime.h>
#include <math.h>

#define NBOX 98
#define NPAIR 49
#define THREADS 256   // 2 images per CTA, 128 threads each

__device__ __forceinline__ float sigm(float v) {
    return 1.0f / (1.0f + __expf(-v));
}

__global__ __launch_bounds__(THREADS, 8) void yolo_post_kernel(
    const float* __restrict__ x, float* __restrict__ out, int B)
{
    __shared__ float s_x[2 * 1470];
    __shared__ __align__(16) unsigned long long s_pair[2 * 50]; // per-half: 49 + pad
    __shared__ int s_wcnt[8];

    const int tid  = threadIdx.x;
    const int half = tid >> 7;          // which image of the pair
    const int ltid = tid & 127;         // thread id within the image
    const int img  = blockIdx.x * 2 + half;

    // ---- stage BOTH input rows (contiguous in gmem -> one coalesced block) ----
    {
        const float2* __restrict__ xin2 =
            (const float2*)(x + (size_t)blockIdx.x * 2 * 1470);
        float2* __restrict__ sx2 = (float2*)s_x;
        #pragma unroll
        for (int it = 0; it < 6; ++it) {
            const int i = tid + it * THREADS;
            if (i < 1470) sx2[i] = xin2[i];
        }
    }
    __syncthreads();

    const float* __restrict__ sx = s_x + half * 1470;

    // output base pointers for my image
    float* __restrict__ p_box = out + (size_t)img * (NBOX * 4);
    float* __restrict__ p_sc  = out + (size_t)B * (NBOX * 4) + (size_t)img * NBOX;
    float* __restrict__ p_lb  = p_sc + (size_t)B * NBOX;
    float* __restrict__ p_kp  = p_lb + (size_t)B * NBOX;

    // ---- decode (convergent; ltid>=98 mapped to cell 48, results unused) ----
    const int bt   = (ltid < NBOX) ? ltid : (96 + (ltid & 1));
    const int cell = bt >> 1;
    const int a    = bt & 1;
    const int ci   = cell / 7;
    const int cj   = cell % 7;
    const int abase = cell * 30 + a * 5;

    // half-argmax over 10 classes + pair merge (anchors share class scores)
    float myb = -INFINITY; int mybl = 0;
    {
        const float2* __restrict__ cp = (const float2*)(sx + cell * 30 + 10) + a * 5;
        const int cb = a * 10;
        #pragma unroll
        for (int c2 = 0; c2 < 5; ++c2) {
            const float2 vv = cp[c2];
            if (vv.x > myb) { myb = vv.x; mybl = cb + 2 * c2; }
            if (vv.y > myb) { myb = vv.y; mybl = cb + 2 * c2 + 1; }
        }
    }
    const float ob  = __shfl_xor_sync(0xFFFFFFFFu, myb, 1);
    const int   obl = __shfl_xor_sync(0xFFFFFFFFu, mybl, 1);
    const float lowb  = a ? ob  : myb;  const int lowl  = a ? obl  : mybl;
    const float highb = a ? myb : ob;   const int highl = a ? mybl : obl;
    const float best = (lowb >= highb) ? lowb : highb;   // first-max == jnp.argmax
    const int   bl   = (lowb >= highb) ? lowl : highl;

    const float to = sx[abase + 4];
    const bool validf = (ltid < NBOX) && (to >= 0.0f);   // sigmoid(to)>=0.5 <=> to>=0

    // coords: cj>=1 forces x1=x2=1 identically (clamp after +64*cj); same for ci in y
    float x1, x2, y1, y2;
    if (cj == 0) {
        const float sx_ = sigm(sx[abase + 0]);
        x1 = sx_; x2 = fminf(sx_ + sigm(sx[abase + 2]), 1.0f);
    } else { x1 = 1.0f; x2 = 1.0f; }
    if (ci == 0) {
        const float sy_ = sigm(sx[abase + 1]);
        y1 = sy_; y2 = fminf(sy_ + sigm(sx[abase + 3]), 1.0f);
    } else { y1 = 1.0f; y2 = 1.0f; }

    // ---- per-pair key entry (one write per pair, by the even-anchor thread) ----
    const unsigned bal = __ballot_sync(0xFFFFFFFFu, validf);
    const int lane = tid & 31;
    const int warp = tid >> 5;           // 0..7 block-wide
    const int hw   = warp & 3;           // warp index within my half
    if (lane == 0) s_wcnt[warp] = __popc(bal);

    // probe key: score descending, then cell index ascending; cnt bits below
    unsigned long long Kme;
    {
        const unsigned u  = __float_as_uint(best);
        const unsigned ou = (u & 0x80000000u) ? ~u : (u | 0x80000000u);
        Kme = (((unsigned long long)(~ou)) << 32) | (unsigned)((2 * cell) << 2);
    }
    const unsigned vother = (bal >> (lane ^ 1)) & 1u;
    if (ltid < NBOX && a == 0) {
        const unsigned cnt = (unsigned)validf + vother;
        s_pair[half * 50 + cell] = Kme | cnt;
    }
    __syncthreads();

    const int wb = half * 4;
    const int V = s_wcnt[wb] + s_wcnt[wb + 1] + s_wcnt[wb + 2] + s_wcnt[wb + 3];

    // ---- rank: convergent parity-split scan, LDS.128 (2 entries/load) ----
    // a=0 covers entries 0..23 (+ entry 48), a=1 covers 24..47; union = all 49.
    // rank(pair leader) = sum cnt over strictly-smaller keys; own entry >= Kme.
    int rk = 0;
    {
        const unsigned long long* __restrict__ sp = s_pair + half * 50;
        const ulonglong2* __restrict__ sp2 = reinterpret_cast<const ulonglong2*>(sp);
        const int base2 = a * 12;
        #pragma unroll
        for (int it = 0; it < 12; ++it) {
            const ulonglong2 e2 = sp2[base2 + it];
            if (e2.x < Kme) rk += (int)(e2.x & 3u);
            if (e2.y < Kme) rk += (int)(e2.y & 3u);
        }
        const unsigned long long e48 = sp[48];
        if (a == 0 && e48 < Kme) rk += (int)(e48 & 3u);
    }
    rk += __shfl_xor_sync(0xFFFFFFFFu, rk, 1);           // full pair-leader rank
    const unsigned pv0 = (bal >> (lane & ~1)) & 1u;      // validity of pair's anchor 0
    const int rank = rk + (a ? (int)pv0 : 0);

    // ---- emit exactly once per output position ----
    if (ltid < NBOX) {
        bool keep = false;
        int pos;
        if (validf) {
            pos = rank;
            keep = (best >= 0.05f);
            // Structural NMS: every box outside cell(0,0) is clamp-degenerate
            // (zero area) for any input => iou==0; orig0/orig1 share a score so
            // orig0 ranks first and is unsuppressible. Only check: orig1 vs orig0.
            if (keep && bt == 1 && sx[4] >= 0.0f) {
                const float a0x1 = sigm(sx[0]);
                const float a0x2 = fminf(a0x1 + sigm(sx[2]), 1.0f);
                const float a0y1 = sigm(sx[1]);
                const float a0y2 = fminf(a0y1 + sigm(sx[3]), 1.0f);
                const float lx = fmaxf(a0x1, x1), ly = fmaxf(a0y1, y1);
                const float rx = fminf(a0x2, x2), ry = fminf(a0y2, y2);
                const float wn = fmaxf(rx - lx, 0.0f), hn = fmaxf(ry - ly, 0.0f);
                const float inter = wn * hn;
                const float uni = (a0x2 - a0x1) * (a0y2 - a0y1)
                                + (x2 - x1) * (y2 - y1) - inter;
                if (uni > 0.0f && inter > 0.7f * uni) keep = false;
            }
        } else {
            // tail slot: V + rank among invalid boxes by original index
            int nvb = __popc(bal & ((1u << lane) - 1u));
            if (hw > 0) nvb += s_wcnt[wb];
            if (hw > 1) nvb += s_wcnt[wb + 1];
            if (hw > 2) nvb += s_wcnt[wb + 2];
            pos = V + (bt - nvb);
        }

        const float4 bb = keep ? make_float4(x1, y1, x2, y2)
                               : make_float4(0.f, 0.f, 0.f, 0.f);
        reinterpret_cast<float4*>(p_box)[pos] = bb;
        p_sc[pos] = keep ? best : 0.f;
        p_lb[pos] = keep ? (float)bl : 0.f;
        p_kp[pos] = keep ? 1.f : 0.f;
    }
}

extern "C" void kernel_launch(void* const* d_in, const int* in_sizes, int n_in,
                              void* d_out, int out_size)
{
    const float* x = (const float*)d_in[0];
    const int B = in_sizes[0] / 1470;   // B = 8192 (even)
    yolo_post_kernel<<<B / 2, THREADS>>>(x, (float*)d_out, B);
}

// round 16
// speedup vs baseline: 1.0427x; 1.0427x over previous
#include <cuda_runtime.h>
#include <math.h>

#define NBOX 98
#define NPAIR 49
#define THREADS 128

__device__ __forceinline__ float sigm(float v) {
    return __fdividef(1.0f, 1.0f + __expf(-v));
}

__global__ __launch_bounds__(THREADS, 16) void yolo_post_kernel(
    const float* __restrict__ x, float* __restrict__ out, int B)
{
    __shared__ __align__(16) float s_x[1472];
    __shared__ __align__(16) unsigned long long s_pair[NPAIR + 1];
    __shared__ int s_wcnt[4];

    const int tid = threadIdx.x;
    const int img = blockIdx.x;

    // output base pointers
    float* __restrict__ p_box = out + (size_t)img * (NBOX * 4);
    float* __restrict__ p_sc  = out + (size_t)B * (NBOX * 4) + (size_t)img * NBOX;
    float* __restrict__ p_lb  = p_sc + (size_t)B * NBOX;
    float* __restrict__ p_kp  = p_lb + (size_t)B * NBOX;

    const int lane = tid & 31, w = tid >> 5;

    // ---- warp-local staging (each warp stages exactly the slice its decode reads) ----
    // Row start F = img*1470 floats; F mod 4 = 2*(img&1) -> align to 16B with shift.
    const int shift = (img & 1) << 1;                 // 0 or 2 floats
    {
        const float4* __restrict__ g4 =
            (const float4*)(x + ((size_t)img * 1470 - shift));
        float4* __restrict__ s4 = (float4*)s_x;
        // warp w decode slice: sx floats [480w, 480w+480) (warp3: [1440,1470))
        // -> s_x float4 range [120w, 120w+121) for w<3, [360,368) for w=3.
        const int sbase = (w < 3) ? (120 * w) : 360;
        const int scnt  = (w < 3) ? 121 : 8;
        #pragma unroll
        for (int it = 0; it < 4; ++it) {
            const int o = lane + 32 * it;
            if (o < scnt) s4[sbase + o] = g4[sbase + o];
        }
    }
    __syncwarp();
    const float* __restrict__ sx = s_x + shift;

    // ---- decode (convergent; threads >=98 mapped to cell 48, results unused) ----
    const int bt   = (tid < NBOX) ? tid : (96 + (tid & 1));
    const int cell = bt >> 1;
    const int a    = bt & 1;
    const int ci   = cell / 7;
    const int cj   = cell % 7;
    const int abase = cell * 30 + a * 5;

    // half-argmax over 10 classes + pair merge (anchors share class scores)
    float myb = -INFINITY; int mybl = 0;
    {
        const float2* __restrict__ cp = (const float2*)(sx + cell * 30 + 10) + a * 5;
        const int cb = a * 10;
        #pragma unroll
        for (int c2 = 0; c2 < 5; ++c2) {
            const float2 vv = cp[c2];
            if (vv.x > myb) { myb = vv.x; mybl = cb + 2 * c2; }
            if (vv.y > myb) { myb = vv.y; mybl = cb + 2 * c2 + 1; }
        }
    }
    const float ob  = __shfl_xor_sync(0xFFFFFFFFu, myb, 1);
    const int   obl = __shfl_xor_sync(0xFFFFFFFFu, mybl, 1);
    const float lowb  = a ? ob  : myb;  const int lowl  = a ? obl  : mybl;
    const float highb = a ? myb : ob;   const int highl = a ? mybl : obl;
    const float best = (lowb >= highb) ? lowb : highb;   // first-max == jnp.argmax
    const int   bl   = (lowb >= highb) ? lowl : highl;

    const float to = sx[abase + 4];
    const bool validf = (tid < NBOX) && (to >= 0.0f);    // sigmoid(to)>=0.5 <=> to>=0

    // coords: cj>=1 forces x1=x2=1 identically (clamp after +64*cj); same for ci in y
    float x1, x2, y1, y2;
    if (cj == 0) {
        const float sx_ = sigm(sx[abase + 0]);
        x1 = sx_; x2 = fminf(sx_ + sigm(sx[abase + 2]), 1.0f);
    } else { x1 = 1.0f; x2 = 1.0f; }
    if (ci == 0) {
        const float sy_ = sigm(sx[abase + 1]);
        y1 = sy_; y2 = fminf(sy_ + sigm(sx[abase + 3]), 1.0f);
    } else { y1 = 1.0f; y2 = 1.0f; }

    // ---- per-pair key entry + warp counts, then the single block barrier ----
    const unsigned bal = __ballot_sync(0xFFFFFFFFu, validf);
    if (lane == 0) s_wcnt[w] = __popc(bal);

    // probe key: score descending, then cell index ascending; cnt bits below
    unsigned long long Kme;
    {
        const unsigned u  = __float_as_uint(best);
        const unsigned ou = (u & 0x80000000u) ? ~u : (u | 0x80000000u);
        Kme = (((unsigned long long)(~ou)) << 32) | (unsigned)((2 * cell) << 2);
    }
    const unsigned vother = (bal >> (lane ^ 1)) & 1u;
    if (tid < NBOX && a == 0) {
        const unsigned cnt = (unsigned)validf + vother;
        s_pair[cell] = Kme | cnt;
    }
    __syncthreads();

    const int c0 = s_wcnt[0], c1 = s_wcnt[1], c2s = s_wcnt[2], c3 = s_wcnt[3];
    const int V = c0 + c1 + c2s + c3;

    // ---- rank: convergent parity-split scan, LDS.128 (2 entries/load) ----
    // a=0 covers entries 0..23 (+ entry 48), a=1 covers 24..47; union = all 49.
    // rank(pair leader) = sum cnt over strictly-smaller keys; own entry >= Kme.
    int rk = 0;
    {
        const ulonglong2* __restrict__ sp2 =
            reinterpret_cast<const ulonglong2*>(s_pair);
        const int base2 = a * 12;
        #pragma unroll
        for (int it = 0; it < 12; ++it) {
            const ulonglong2 e2 = sp2[base2 + it];
            if (e2.x < Kme) rk += (int)(e2.x & 3u);
            if (e2.y < Kme) rk += (int)(e2.y & 3u);
        }
        const unsigned long long e48 = s_pair[48];
        if (a == 0 && e48 < Kme) rk += (int)(e48 & 3u);
    }
    rk += __shfl_xor_sync(0xFFFFFFFFu, rk, 1);           // full pair-leader rank
    const unsigned pv0 = (bal >> (lane & ~1)) & 1u;      // validity of pair's anchor 0
    const int rank = rk + (a ? (int)pv0 : 0);

    // ---- emit exactly once per output position ----
    if (tid < NBOX) {
        bool keep = false;
        int pos;
        if (validf) {
            pos = rank;
            keep = (best >= 0.05f);
            // Structural NMS: every box outside cell(0,0) is clamp-degenerate
            // (zero area) for any input => iou==0; orig0/orig1 share a score so
            // orig0 ranks first and is unsuppressible. Only check: orig1 vs orig0.
            if (keep && bt == 1 && sx[4] >= 0.0f) {
                const float a0x1 = sigm(sx[0]);
                const float a0x2 = fminf(a0x1 + sigm(sx[2]), 1.0f);
                const float a0y1 = sigm(sx[1]);
                const float a0y2 = fminf(a0y1 + sigm(sx[3]), 1.0f);
                const float lx = fmaxf(a0x1, x1), ly = fmaxf(a0y1, y1);
                const float rx = fminf(a0x2, x2), ry = fminf(a0y2, y2);
                const float wn = fmaxf(rx - lx, 0.0f), hn = fmaxf(ry - ly, 0.0f);
                const float inter = wn * hn;
                const float uni = (a0x2 - a0x1) * (a0y2 - a0y1)
                                + (x2 - x1) * (y2 - y1) - inter;
                if (uni > 0.0f && inter > 0.7f * uni) keep = false;
            }
        } else {
            // tail slot: V + rank among invalid boxes by original index
            int nvb = __popc(bal & ((1u << lane) - 1u));
            if (w > 0) nvb += c0;
            if (w > 1) nvb += c1;
            if (w > 2) nvb += c2s;
            pos = V + (bt - nvb);
        }

        const float4 bb = keep ? make_float4(x1, y1, x2, y2)
                               : make_float4(0.f, 0.f, 0.f, 0.f);
        reinterpret_cast<float4*>(p_box)[pos] = bb;
        p_sc[pos] = keep ? best : 0.f;
        p_lb[pos] = keep ? (float)bl : 0.f;
        p_kp[pos] = keep ? 1.f : 0.f;
    }
}

extern "C" void kernel_launch(void* const* d_in, const int* in_sizes, int n_in,
                              void* d_out, int out_size)
{
    const float* x = (const float*)d_in[0];
    const int B = in_sizes[0] / 1470;
    yolo_post_kernel<<<B, THREADS>>>(x, (float*)d_out, B);
}

// round 17
// speedup vs baseline: 1.0475x; 1.0046x over previous
#include <cuda_runtime.h>
#include <math.h>

#define NBOX 98
#define THREADS 128   // 4 warps = 4 images per CTA, warp-autonomous

__device__ __forceinline__ float sigm(float v) {
    return __fdividef(1.0f, 1.0f + __expf(-v));
}

struct PairDec {
    float x1[2], y1[2], x2[2], y2[2];
    float best; int bl;
    bool v0, v1;
    unsigned long long K;   // probe key (cnt bits zero)
};

__device__ __forceinline__ void decode_cell(const float* __restrict__ sx, int c, PairDec& P)
{
    const int base = c * 30;
    // class argmax over 20 (first-max == jnp.argmax); float2 loads (8B aligned)
    const float2* __restrict__ cp = (const float2*)(sx + base + 10);
    float best = -INFINITY; int bl = 0;
    #pragma unroll
    for (int i = 0; i < 10; ++i) {
        const float2 v = cp[i];
        if (v.x > best) { best = v.x; bl = 2 * i; }
        if (v.y > best) { best = v.y; bl = 2 * i + 1; }
    }
    P.best = best; P.bl = bl;
    P.v0 = sx[base + 4] >= 0.0f;    // sigmoid(obj)>=0.5 <=> raw>=0
    P.v1 = sx[base + 9] >= 0.0f;
    const int cj = c % 7, ci = c / 7;
    #pragma unroll
    for (int a = 0; a < 2; ++a) {
        const int ab = base + a * 5;
        float x1, x2, y1, y2;
        // cj>=1 forces x1=x2=1 identically (clamp after +64*cj); same for ci in y
        if (cj == 0) {
            const float s = sigm(sx[ab + 0]);
            x1 = s; x2 = fminf(s + sigm(sx[ab + 2]), 1.0f);
        } else { x1 = 1.0f; x2 = 1.0f; }
        if (ci == 0) {
            const float s = sigm(sx[ab + 1]);
            y1 = s; y2 = fminf(s + sigm(sx[ab + 3]), 1.0f);
        } else { y1 = 1.0f; y2 = 1.0f; }
        P.x1[a] = x1; P.x2[a] = x2; P.y1[a] = y1; P.y2[a] = y2;
    }
    // key: score descending, then cell index ascending; cnt bits [0,2) left zero
    const unsigned u  = __float_as_uint(best);
    const unsigned ou = (u & 0x80000000u) ? ~u : (u | 0x80000000u);
    P.K = (((unsigned long long)(~ou)) << 32) | (unsigned)((2 * c) << 2);
}

__global__ __launch_bounds__(THREADS, 8) void yolo_post_kernel(
    const float* __restrict__ x, float* __restrict__ out, int B)
{
    __shared__ __align__(16) float s_x[4 * 1472];
    __shared__ __align__(16) unsigned long long s_pair[4][50];  // 49 + max-pad

    const int tid = threadIdx.x, lane = tid & 31, w = tid >> 5;
    const int img = blockIdx.x * 4 + w;
    if (img >= B) return;                       // whole warp exits together

    // ---- warp-local staging (coalesced float4; 16B-align via even shift) ----
    // Row float-start F = img*1470; F mod 4 = 2*(img&1). For odd img the shifted
    // window [F-2, F+1470) stays in bounds and ends exactly at the row end.
    const int shift = (img & 1) << 1;
    {
        const float4* __restrict__ g4 =
            (const float4*)(x + ((size_t)img * 1470 - shift));
        float4* __restrict__ s4 = (float4*)(s_x + w * 1472);
        #pragma unroll
        for (int it = 0; it < 12; ++it) {
            const int o = lane + 32 * it;
            if (o < 368) s4[o] = g4[o];
        }
    }
    __syncwarp();
    const float* __restrict__ sx = s_x + w * 1472 + shift;

    // output base pointers
    float* __restrict__ p_box = out + (size_t)img * (NBOX * 4);
    float* __restrict__ p_sc  = out + (size_t)B * (NBOX * 4) + (size_t)img * NBOX;
    float* __restrict__ p_lb  = p_sc + (size_t)B * NBOX;
    float* __restrict__ p_kp  = p_lb + (size_t)B * NBOX;

    // ---- decode: lane owns cell A=lane (0..31) and cell B=32+lane (lane<17) ----
    PairDec A, Bp;
    Bp.K = 0;                                   // !hasB: probe matches nothing
    Bp.v0 = Bp.v1 = false;
    decode_cell(sx, lane, A);
    const bool hasB = (lane < 17);
    const int cB = 32 + lane;
    if (hasB) decode_cell(sx, cB, Bp);

    // ---- valid counts / prefixes via ballots (no smem bookkeeping) ----
    const unsigned balA0 = __ballot_sync(0xFFFFFFFFu, A.v0);
    const unsigned balA1 = __ballot_sync(0xFFFFFFFFu, A.v1);
    const unsigned balB0 = __ballot_sync(0xFFFFFFFFu, Bp.v0);
    const unsigned balB1 = __ballot_sync(0xFFFFFFFFu, Bp.v1);
    const int sumA = __popc(balA0) + __popc(balA1);
    const int V = sumA + __popc(balB0) + __popc(balB1);
    const unsigned lm = (1u << lane) - 1u;
    const int pcA = __popc(balA0 & lm) + __popc(balA1 & lm);           // valid in cells < lane
    const int pcB = sumA + __popc(balB0 & lm) + __popc(balB1 & lm);    // valid in cells < 32+lane

    // ---- pair table (per-warp), then warp-only sync ----
    unsigned long long* __restrict__ sp = s_pair[w];
    sp[lane] = A.K | (unsigned)((int)A.v0 + (int)A.v1);
    if (hasB) sp[cB] = Bp.K | (unsigned)((int)Bp.v0 + (int)Bp.v1);
    if (lane == 17) sp[49] = ~0ull;             // pad entry, never < any probe
    __syncwarp();

    // ---- dual-probe rank scan: one LDS.128 pass ranks BOTH of my pairs ----
    // rank(pair leader) = sum cnt over strictly-smaller keys; own entry >= K.
    int rkA = 0, rkB = 0;
    {
        const ulonglong2* __restrict__ sp2 = (const ulonglong2*)sp;
        #pragma unroll
        for (int i = 0; i < 25; ++i) {
            const ulonglong2 e = sp2[i];
            if (e.x < A.K)  rkA += (int)(e.x & 3u);
            if (e.y < A.K)  rkA += (int)(e.y & 3u);
            if (e.x < Bp.K) rkB += (int)(e.x & 3u);
            if (e.y < Bp.K) rkB += (int)(e.y & 3u);
        }
    }

    // ---- emit: exactly one write per output position ----
    // valid box -> its rank; invalid box -> V + (orig_idx - #valid before it).
    #define EMIT_PAIR(P, c, rk, pc)                                               \
    {                                                                             \
        _Pragma("unroll")                                                         \
        for (int a = 0; a < 2; ++a) {                                             \
            const bool valid = a ? (P).v1 : (P).v0;                               \
            bool keep = false;                                                    \
            int pos;                                                              \
            if (valid) {                                                          \
                pos = a ? ((rk) + (int)(P).v0) : (rk);                            \
                keep = ((P).best >= 0.05f);                                       \
                /* Structural NMS: only orig idx 1 (cell0,a1) can be suppressed   \
                   (by orig 0); all boxes outside cell(0,0) are clamp-degenerate  \
                   for any input, and the cell-0 pair shares a score so orig0     \
                   ranks first and is unsuppressible. */                          \
                if (a == 1 && (c) == 0 && keep && (P).v0) {                       \
                    const float lx = fmaxf((P).x1[0], (P).x1[1]);                 \
                    const float ly = fmaxf((P).y1[0], (P).y1[1]);                 \
                    const float rx = fminf((P).x2[0], (P).x2[1]);                 \
                    const float ry = fminf((P).y2[0], (P).y2[1]);                 \
                    const float wn = fmaxf(rx - lx, 0.0f);                        \
                    const float hn = fmaxf(ry - ly, 0.0f);                        \
                    const float inter = wn * hn;                                  \
                    const float uni =                                             \
                        ((P).x2[0] - (P).x1[0]) * ((P).y2[0] - (P).y1[0]) +       \
                        ((P).x2[1] - (P).x1[1]) * ((P).y2[1] - (P).y1[1]) - inter;\
                    if (uni > 0.0f && inter > 0.7f * uni) keep = false;           \
                }                                                                 \
            } else {                                                              \
                pos = V + (2 * (c) + a) - ((pc) + (a ? (int)(P).v0 : 0));         \
            }                                                                     \
            const float4 bb = keep                                                \
                ? make_float4((P).x1[a], (P).y1[a], (P).x2[a], (P).y2[a])         \
                : make_float4(0.f, 0.f, 0.f, 0.f);                                \
            reinterpret_cast<float4*>(p_box)[pos] = bb;                           \
            p_sc[pos] = keep ? (P).best : 0.f;                                    \
            p_lb[pos] = keep ? (float)(P).bl : 0.f;                               \
            p_kp[pos] = keep ? 1.f : 0.f;                                         \
        }                                                                         \
    }

    EMIT_PAIR(A, lane, rkA, pcA);
    if (hasB) EMIT_PAIR(Bp, cB, rkB, pcB);
    #undef EMIT_PAIR
}

extern "C" void kernel_launch(void* const* d_in, const int* in_sizes, int n_in,
                              void* d_out, int out_size)
{
    const float* x = (const float*)d_in[0];
    const int B = in_sizes[0] / 1470;           // 8192
    yolo_post_kernel<<<(B + 3) / 4, THREADS>>>(x, (float*)d_out, B);
}